// round 15
// baseline (speedup 1.0000x reference)
#include <cuda_runtime.h>

#define THREADS 128
#define EPSF 1e-12f

typedef unsigned long long ull;

// ---- f32x2 packed helpers (sm_103a) ----
__device__ __forceinline__ ull pack2(float lo, float hi) {
    ull r; asm("mov.b64 %0, {%1, %2};" : "=l"(r) : "f"(lo), "f"(hi)); return r;
}
__device__ __forceinline__ void unpack2(ull p, float& lo, float& hi) {
    asm("mov.b64 {%0, %1}, %2;" : "=f"(lo), "=f"(hi) : "l"(p));
}
__device__ __forceinline__ ull fma2(ull a, ull b, ull c) {
    ull d; asm("fma.rn.f32x2 %0, %1, %2, %3;" : "=l"(d) : "l"(a), "l"(b), "l"(c)); return d;
}
__device__ __forceinline__ ull add2(ull a, ull b) {
    ull d; asm("add.rn.f32x2 %0, %1, %2;" : "=l"(d) : "l"(a), "l"(b)); return d;
}
__device__ __forceinline__ ull mul2(ull a, ull b) {
    ull d; asm("mul.rn.f32x2 %0, %1, %2;" : "=l"(d) : "l"(a), "l"(b)); return d;
}
__device__ __forceinline__ float frcp(float x) {
    float y; asm("rcp.approx.f32 %0, %1;" : "=f"(y) : "f"(x)); return y;
}

__global__ __launch_bounds__(THREADS, 5)
void sinkhorn_unmatched_kernel(
    const float* __restrict__ margins,
    const float* __restrict__ W1, const float* __restrict__ b1,
    const float* __restrict__ W2, const float* __restrict__ b2,
    const float* __restrict__ W3, const float* __restrict__ b3,
    const float* __restrict__ W4, const float* __restrict__ b4,
    float* __restrict__ out_mus, float* __restrict__ out_V, int B)
{
    // W1 transposed into output-pair rows: sW1t[jp][2*i+s] = W1[i][2*jp+s]
    __shared__ float sW1t[32 * 12];
    __shared__ ull   sb1p[32];        // (b1[2jp], b1[2jp+1])
    __shared__ float sW2[64 * 32];
    __shared__ float sb2[32];
    __shared__ float sW3[32 * 16];
    __shared__ float sb3[16];
    __shared__ float sW4[16 * 12];
    __shared__ float sb4[12];

    const int tid = threadIdx.x;
    for (int i = tid; i < 32 * 12; i += THREADS) {
        int jp = i / 12, t = i % 12;
        int in = t >> 1, s = t & 1;
        sW1t[i] = W1[in * 64 + 2 * jp + s];
    }
    for (int i = tid; i < 32; i += THREADS) sb1p[i] = pack2(b1[2 * i], b1[2 * i + 1]);
    for (int i = tid; i < 64 * 32; i += THREADS) sW2[i] = W2[i];
    for (int i = tid; i < 32; i += THREADS) sb2[i] = b2[i];
    for (int i = tid; i < 32 * 16; i += THREADS) sW3[i] = W3[i];
    for (int i = tid; i < 16; i += THREADS) sb3[i] = b3[i];
    for (int i = tid; i < 16 * 12; i += THREADS) {
        int r = i / 12, c = i % 12;
        sW4[i] = (c < 9) ? W4[r * 9 + c] : 0.0f;
    }
    for (int i = tid; i < 12; i += THREADS) sb4[i] = (i < 9) ? b4[i] : 0.0f;

    int rowA = blockIdx.x * (2 * THREADS) + tid;
    int rowB = rowA + THREADS;
    if (rowA >= B) { __syncthreads(); return; }
    if (rowB >= B) rowB = rowA;

    // margins: self-duplicated pairs per row (live only through the L1/L2 loop)
    const float2* m2 = reinterpret_cast<const float2*>(margins);
    ull pxA[6], pxB[6];
    {
        float2 a0 = m2[rowA * 3 + 0], a1 = m2[rowA * 3 + 1], a2 = m2[rowA * 3 + 2];
        float2 b0 = m2[rowB * 3 + 0], b1v = m2[rowB * 3 + 1], b2v = m2[rowB * 3 + 2];
        pxA[0] = pack2(a0.x, a0.x);   pxA[1] = pack2(a0.y, a0.y);
        pxA[2] = pack2(a1.x, a1.x);   pxA[3] = pack2(a1.y, a1.y);
        pxA[4] = pack2(a2.x, a2.x);   pxA[5] = pack2(a2.y, a2.y);
        pxB[0] = pack2(b0.x, b0.x);   pxB[1] = pack2(b0.y, b0.y);
        pxB[2] = pack2(b1v.x, b1v.x); pxB[3] = pack2(b1v.y, b1v.y);
        pxB[4] = pack2(b2v.x, b2v.x); pxB[5] = pack2(b2v.y, b2v.y);
    }

    __syncthreads();

    // ---- fused L1 (6->64 as 32 output-pairs) + full-width L2 (64->32) ----
    ull accA[16], accB[16];
    {
        const ulonglong2* bias = reinterpret_cast<const ulonglong2*>(sb2);
        #pragma unroll
        for (int q = 0; q < 8; q++) {
            ulonglong2 t = bias[q];
            accA[2 * q] = t.x; accA[2 * q + 1] = t.y;
            accB[2 * q] = t.x; accB[2 * q + 1] = t.y;
        }
    }
    #pragma unroll 4
    for (int jp = 0; jp < 32; jp++) {
        const ulonglong2* w1 = reinterpret_cast<const ulonglong2*>(sW1t + jp * 12);
        ulonglong2 wa = w1[0], wb = w1[1], wc = w1[2];
        ull bp = sb1p[jp];
        ull hA = fma2(pxA[0], wa.x, bp);
        hA = fma2(pxA[1], wa.y, hA);
        hA = fma2(pxA[2], wb.x, hA);
        hA = fma2(pxA[3], wb.y, hA);
        hA = fma2(pxA[4], wc.x, hA);
        hA = fma2(pxA[5], wc.y, hA);
        ull hB = fma2(pxB[0], wa.x, bp);
        hB = fma2(pxB[1], wa.y, hB);
        hB = fma2(pxB[2], wb.x, hB);
        hB = fma2(pxB[3], wb.y, hB);
        hB = fma2(pxB[4], wc.x, hB);
        hB = fma2(pxB[5], wc.y, hB);
        float h0A, h1A, h0B, h1B;
        unpack2(hA, h0A, h1A);
        unpack2(hB, h0B, h1B);
        h0A = fmaxf(h0A, 0.0f); h1A = fmaxf(h1A, 0.0f);
        h0B = fmaxf(h0B, 0.0f); h1B = fmaxf(h1B, 0.0f);
        // j = 2*jp : full 32-wide W2 row
        {
            ull paa = pack2(h0A, h0A), pbb = pack2(h0B, h0B);
            const ulonglong2* w2 = reinterpret_cast<const ulonglong2*>(sW2 + (2 * jp) * 32);
            #pragma unroll
            for (int q = 0; q < 8; q++) {
                ulonglong2 w = w2[q];
                accA[2 * q]     = fma2(paa, w.x, accA[2 * q]);
                accA[2 * q + 1] = fma2(paa, w.y, accA[2 * q + 1]);
                accB[2 * q]     = fma2(pbb, w.x, accB[2 * q]);
                accB[2 * q + 1] = fma2(pbb, w.y, accB[2 * q + 1]);
            }
        }
        // j = 2*jp + 1
        {
            ull paa = pack2(h1A, h1A), pbb = pack2(h1B, h1B);
            const ulonglong2* w2 = reinterpret_cast<const ulonglong2*>(sW2 + (2 * jp + 1) * 32);
            #pragma unroll
            for (int q = 0; q < 8; q++) {
                ulonglong2 w = w2[q];
                accA[2 * q]     = fma2(paa, w.x, accA[2 * q]);
                accA[2 * q + 1] = fma2(paa, w.y, accA[2 * q + 1]);
                accB[2 * q]     = fma2(pbb, w.x, accB[2 * q]);
                accB[2 * q + 1] = fma2(pbb, w.y, accB[2 * q + 1]);
            }
        }
    }

    // ---- L3 (32->16): consume full acc (explicit s=0/s=1) ----
    ull h3A[8], h3B[8];
    {
        const ulonglong2* bias = reinterpret_cast<const ulonglong2*>(sb3);
        #pragma unroll
        for (int q = 0; q < 4; q++) {
            ulonglong2 t = bias[q];
            h3A[2 * q] = t.x; h3A[2 * q + 1] = t.y;
            h3B[2 * q] = t.x; h3B[2 * q + 1] = t.y;
        }
    }
    #pragma unroll 4
    for (int p = 0; p < 16; p++) {
        float a0f, a1f, b0f, b1f;
        unpack2(accA[p], a0f, a1f);
        unpack2(accB[p], b0f, b1f);
        a0f = fmaxf(a0f, 0.0f); a1f = fmaxf(a1f, 0.0f);
        b0f = fmaxf(b0f, 0.0f); b1f = fmaxf(b1f, 0.0f);
        {
            const int j3 = 2 * p;
            ull paa = pack2(a0f, a0f), pbb = pack2(b0f, b0f);
            const ulonglong2* w3 = reinterpret_cast<const ulonglong2*>(sW3 + j3 * 16);
            #pragma unroll
            for (int q = 0; q < 4; q++) {
                ulonglong2 w = w3[q];
                h3A[2 * q]     = fma2(paa, w.x, h3A[2 * q]);
                h3A[2 * q + 1] = fma2(paa, w.y, h3A[2 * q + 1]);
                h3B[2 * q]     = fma2(pbb, w.x, h3B[2 * q]);
                h3B[2 * q + 1] = fma2(pbb, w.y, h3B[2 * q + 1]);
            }
        }
        {
            const int j3 = 2 * p + 1;
            ull paa = pack2(a1f, a1f), pbb = pack2(b1f, b1f);
            const ulonglong2* w3 = reinterpret_cast<const ulonglong2*>(sW3 + j3 * 16);
            #pragma unroll
            for (int q = 0; q < 4; q++) {
                ulonglong2 w = w3[q];
                h3A[2 * q]     = fma2(paa, w.x, h3A[2 * q]);
                h3A[2 * q + 1] = fma2(paa, w.y, h3A[2 * q + 1]);
                h3B[2 * q]     = fma2(pbb, w.x, h3B[2 * q]);
                h3B[2 * q + 1] = fma2(pbb, w.y, h3B[2 * q + 1]);
            }
        }
    }

    // ---- L4 (16->9, padded 12), explicit s=0/s=1 ----
    ull pAa[6], pBa[6];
    {
        const ulonglong2* bias = reinterpret_cast<const ulonglong2*>(sb4);
        #pragma unroll
        for (int q = 0; q < 3; q++) {
            ulonglong2 t = bias[q];
            pAa[2 * q] = t.x; pAa[2 * q + 1] = t.y;
            pBa[2 * q] = t.x; pBa[2 * q + 1] = t.y;
        }
    }
    #pragma unroll
    for (int jp = 0; jp < 8; jp++) {
        float a0f, a1f, b0f, b1f;
        unpack2(h3A[jp], a0f, a1f);
        unpack2(h3B[jp], b0f, b1f);
        a0f = fmaxf(a0f, 0.0f); a1f = fmaxf(a1f, 0.0f);
        b0f = fmaxf(b0f, 0.0f); b1f = fmaxf(b1f, 0.0f);
        {
            const int j = 2 * jp;
            ull paa = pack2(a0f, a0f), pbb = pack2(b0f, b0f);
            const ulonglong2* w4 = reinterpret_cast<const ulonglong2*>(sW4 + j * 12);
            #pragma unroll
            for (int q = 0; q < 3; q++) {
                ulonglong2 w = w4[q];
                pAa[2 * q]     = fma2(paa, w.x, pAa[2 * q]);
                pAa[2 * q + 1] = fma2(paa, w.y, pAa[2 * q + 1]);
                pBa[2 * q]     = fma2(pbb, w.x, pBa[2 * q]);
                pBa[2 * q + 1] = fma2(pbb, w.y, pBa[2 * q + 1]);
            }
        }
        {
            const int j = 2 * jp + 1;
            ull paa = pack2(a1f, a1f), pbb = pack2(b1f, b1f);
            const ulonglong2* w4 = reinterpret_cast<const ulonglong2*>(sW4 + j * 12);
            #pragma unroll
            for (int q = 0; q < 3; q++) {
                ulonglong2 w = w4[q];
                pAa[2 * q]     = fma2(paa, w.x, pAa[2 * q]);
                pAa[2 * q + 1] = fma2(paa, w.y, pAa[2 * q + 1]);
                pBa[2 * q]     = fma2(pbb, w.x, pBa[2 * q]);
                pBa[2 * q + 1] = fma2(pbb, w.y, pBa[2 * q + 1]);
            }
        }
    }

    float parsA[12], parsB[12];
    #pragma unroll
    for (int q = 0; q < 6; q++) {
        unpack2(pAa[q], parsA[2 * q], parsA[2 * q + 1]);
        unpack2(pBa[q], parsB[2 * q], parsB[2 * q + 1]);
    }

    // ---- head math (margins reloaded from gmem; packed over the row pair) ----
    ull A00 = pack2(__expf(parsA[0]), __expf(parsB[0]));
    ull A01 = pack2(__expf(parsA[1]), __expf(parsB[1]));
    ull A10 = pack2(__expf(parsA[2]), __expf(parsB[2]));
    ull A11 = pack2(__expf(parsA[3]), __expf(parsB[3]));
    const ull ONE = pack2(1.0f, 1.0f);
    ull A02 = ONE, A12 = ONE, A20 = ONE, A21 = ONE, A22 = ONE;

    float shm0A = 0.02f + 0.96f * frcp(1.0f + __expf(-parsA[4]));
    float shm1A = 0.02f + 0.96f * frcp(1.0f + __expf(-parsA[5]));
    float shf0A = 0.02f + 0.96f * frcp(1.0f + __expf(-parsA[6]));
    float shf1A = 0.02f + 0.96f * frcp(1.0f + __expf(-parsA[7]));
    float shm0B = 0.02f + 0.96f * frcp(1.0f + __expf(-parsB[4]));
    float shm1B = 0.02f + 0.96f * frcp(1.0f + __expf(-parsB[5]));
    float shf0B = 0.02f + 0.96f * frcp(1.0f + __expf(-parsB[6]));
    float shf1B = 0.02f + 0.96f * frcp(1.0f + __expf(-parsB[7]));
    float VA = __expf(parsA[8]), VB = __expf(parsB[8]);

    float2 a0 = m2[rowA * 3 + 0], a1 = m2[rowA * 3 + 1], a2 = m2[rowA * 3 + 2];
    float2 b0 = m2[rowB * 3 + 0], b1v = m2[rowB * 3 + 1], b2v = m2[rowB * 3 + 2];
    float xA[6] = { a0.x, a0.y, a1.x, a1.y, a2.x, a2.y };
    float xB[6] = { b0.x, b0.y, b1v.x, b1v.y, b2v.x, b2v.y };

    ull M0 = pack2(xA[0], xB[0]), M1 = pack2(xA[1], xB[1]), M2 = pack2(xA[2], xB[2]);
    ull F0 = pack2(xA[3], xB[3]), F1 = pack2(xA[4], xB[4]), F2 = pack2(xA[5], xB[5]);
    ull r0 = mul2(M0, pack2(shm0A, shm0B));
    ull r1 = mul2(M1, pack2(shm1A, shm1B));
    ull r2 = M2;
    ull c0 = mul2(F0, pack2(shf0A, shf0B));
    ull c1 = mul2(F1, pack2(shf1A, shf1B));
    ull c2 = F2;

    float um0A = xA[0] * (1.0f - shm0A), um1A = xA[1] * (1.0f - shm1A);
    float uf0A = xA[3] * (1.0f - shf0A), uf1A = xA[4] * (1.0f - shf1A);
    float um0B = xB[0] * (1.0f - shm0B), um1B = xB[1] * (1.0f - shm1B);
    float uf0B = xB[3] * (1.0f - shf0B), uf1B = xB[4] * (1.0f - shf1B);

    const ull EPS2 = pack2(EPSF, EPSF);

    #pragma unroll
    for (int it = 0; it < 10; it++) {
        ull s0 = add2(add2(A00, A01), add2(A02, EPS2));
        ull s1 = add2(add2(A10, A11), add2(A12, EPS2));
        ull s2 = add2(add2(A20, A21), add2(A22, EPS2));
        float l, h;
        unpack2(s0, l, h); ull i0 = pack2(frcp(l), frcp(h));
        unpack2(s1, l, h); ull i1 = pack2(frcp(l), frcp(h));
        unpack2(s2, l, h); ull i2 = pack2(frcp(l), frcp(h));
        ull f0 = mul2(r0, i0), f1 = mul2(r1, i1), f2 = mul2(r2, i2);
        A00 = mul2(A00, f0); A01 = mul2(A01, f0); A02 = mul2(A02, f0);
        A10 = mul2(A10, f1); A11 = mul2(A11, f1); A12 = mul2(A12, f1);
        A20 = mul2(A20, f2); A21 = mul2(A21, f2); A22 = mul2(A22, f2);
        ull t0 = add2(add2(A00, A10), add2(A20, EPS2));
        ull t1 = add2(add2(A01, A11), add2(A21, EPS2));
        ull t2 = add2(add2(A02, A12), add2(A22, EPS2));
        unpack2(t0, l, h); ull j0 = pack2(frcp(l), frcp(h));
        unpack2(t1, l, h); ull j1 = pack2(frcp(l), frcp(h));
        unpack2(t2, l, h); ull j2 = pack2(frcp(l), frcp(h));
        ull g0 = mul2(c0, j0), g1 = mul2(c1, j1), g2 = mul2(c2, j2);
        A00 = mul2(A00, g0); A10 = mul2(A10, g0); A20 = mul2(A20, g0);
        A01 = mul2(A01, g1); A11 = mul2(A11, g1); A21 = mul2(A21, g1);
        A02 = mul2(A02, g2); A12 = mul2(A12, g2); A22 = mul2(A22, g2);
    }

    float o00, o01, o02, o10, o11, o12, o20, o21, o22;
    float q00, q01, q02, q10, q11, q12, q20, q21, q22;
    unpack2(A00, o00, q00); unpack2(A01, o01, q01); unpack2(A02, o02, q02);
    unpack2(A10, o10, q10); unpack2(A11, o11, q11); unpack2(A12, o12, q12);
    unpack2(A20, o20, q20); unpack2(A21, o21, q21); unpack2(A22, o22, q22);

    float4* oA = reinterpret_cast<float4*>(out_mus + (size_t)rowA * 16);
    oA[0] = make_float4(o00, o01, o02, um0A);
    oA[1] = make_float4(o10, o11, o12, um1A);
    oA[2] = make_float4(o20, o21, o22, 0.0f);
    oA[3] = make_float4(uf0A, uf1A, 0.0f, 0.0f);
    out_V[rowA] = VA;

    float4* oB = reinterpret_cast<float4*>(out_mus + (size_t)rowB * 16);
    oB[0] = make_float4(q00, q01, q02, um0B);
    oB[1] = make_float4(q10, q11, q12, um1B);
    oB[2] = make_float4(q20, q21, q22, 0.0f);
    oB[3] = make_float4(uf0B, uf1B, 0.0f, 0.0f);
    out_V[rowB] = VB;
}

extern "C" void kernel_launch(void* const* d_in, const int* in_sizes, int n_in,
                              void* d_out, int out_size)
{
    const float* margins = (const float*)d_in[0];
    const float* W1 = (const float*)d_in[1];
    const float* b1 = (const float*)d_in[2];
    const float* W2 = (const float*)d_in[3];
    const float* b2 = (const float*)d_in[4];
    const float* W3 = (const float*)d_in[5];
    const float* b3 = (const float*)d_in[6];
    const float* W4 = (const float*)d_in[7];
    const float* b4 = (const float*)d_in[8];

    int B = in_sizes[0] / 6;
    float* out_mus = (float*)d_out;
    float* out_V = (float*)d_out + (size_t)B * 16;

    int rows_per_block = 2 * THREADS;
    int blocks = (B + rows_per_block - 1) / rows_per_block;
    sinkhorn_unmatched_kernel<<<blocks, THREADS>>>(
        margins, W1, b1, W2, b2, W3, b3, W4, b4, out_mus, out_V, B);
}

// round 16
// speedup vs baseline: 1.2927x; 1.2927x over previous
#include <cuda_runtime.h>

#define THREADS 128
#define EPSF 1e-12f

typedef unsigned long long ull;

// ---- f32x2 packed helpers (sm_103a) ----
__device__ __forceinline__ ull pack2(float lo, float hi) {
    ull r; asm("mov.b64 %0, {%1, %2};" : "=l"(r) : "f"(lo), "f"(hi)); return r;
}
__device__ __forceinline__ void unpack2(ull p, float& lo, float& hi) {
    asm("mov.b64 {%0, %1}, %2;" : "=f"(lo), "=f"(hi) : "l"(p));
}
__device__ __forceinline__ ull fma2(ull a, ull b, ull c) {
    ull d; asm("fma.rn.f32x2 %0, %1, %2, %3;" : "=l"(d) : "l"(a), "l"(b), "l"(c)); return d;
}
__device__ __forceinline__ ull add2(ull a, ull b) {
    ull d; asm("add.rn.f32x2 %0, %1, %2;" : "=l"(d) : "l"(a), "l"(b)); return d;
}
__device__ __forceinline__ ull mul2(ull a, ull b) {
    ull d; asm("mul.rn.f32x2 %0, %1, %2;" : "=l"(d) : "l"(a), "l"(b)); return d;
}
__device__ __forceinline__ float frcp(float x) {
    float y; asm("rcp.approx.f32 %0, %1;" : "=f"(y) : "f"(x)); return y;
}

__global__ __launch_bounds__(THREADS, 5)
void sinkhorn_unmatched_kernel(
    const float* __restrict__ margins,
    const float* __restrict__ W1, const float* __restrict__ b1,
    const float* __restrict__ W2, const float* __restrict__ b2,
    const float* __restrict__ W3, const float* __restrict__ b3,
    const float* __restrict__ W4, const float* __restrict__ b4,
    float* __restrict__ out_mus, float* __restrict__ out_V, int B)
{
    // W1 transposed into output-pair rows: sW1t[jp][2*i+s] = W1[i][2*jp+s]
    __shared__ float sW1t[32 * 12];
    __shared__ ull   sb1p[32];        // (b1[2jp], b1[2jp+1])
    __shared__ float sW2[64 * 32];
    __shared__ float sb2[32];
    __shared__ float sW3[32 * 16];
    __shared__ float sb3[16];
    __shared__ float sW4[16 * 12];
    __shared__ float sb4[12];

    const int tid = threadIdx.x;
    for (int i = tid; i < 32 * 12; i += THREADS) {
        int jp = i / 12, t = i % 12;
        int in = t >> 1, s = t & 1;
        sW1t[i] = W1[in * 64 + 2 * jp + s];
    }
    for (int i = tid; i < 32; i += THREADS) sb1p[i] = pack2(b1[2 * i], b1[2 * i + 1]);
    for (int i = tid; i < 64 * 32; i += THREADS) sW2[i] = W2[i];
    for (int i = tid; i < 32; i += THREADS) sb2[i] = b2[i];
    for (int i = tid; i < 32 * 16; i += THREADS) sW3[i] = W3[i];
    for (int i = tid; i < 16; i += THREADS) sb3[i] = b3[i];
    for (int i = tid; i < 16 * 12; i += THREADS) {
        int r = i / 12, c = i % 12;
        sW4[i] = (c < 9) ? W4[r * 9 + c] : 0.0f;
    }
    for (int i = tid; i < 12; i += THREADS) sb4[i] = (i < 9) ? b4[i] : 0.0f;

    int rowA = blockIdx.x * (2 * THREADS) + tid;
    int rowB = rowA + THREADS;
    if (rowA >= B) { __syncthreads(); return; }
    if (rowB >= B) rowB = rowA;

    // margins: self-duplicated pairs per row (live through the L1/L2 loops)
    const float2* m2 = reinterpret_cast<const float2*>(margins);
    ull pxA[6], pxB[6];
    {
        float2 a0 = m2[rowA * 3 + 0], a1 = m2[rowA * 3 + 1], a2 = m2[rowA * 3 + 2];
        float2 b0 = m2[rowB * 3 + 0], b1v = m2[rowB * 3 + 1], b2v = m2[rowB * 3 + 2];
        pxA[0] = pack2(a0.x, a0.x);   pxA[1] = pack2(a0.y, a0.y);
        pxA[2] = pack2(a1.x, a1.x);   pxA[3] = pack2(a1.y, a1.y);
        pxA[4] = pack2(a2.x, a2.x);   pxA[5] = pack2(a2.y, a2.y);
        pxB[0] = pack2(b0.x, b0.x);   pxB[1] = pack2(b0.y, b0.y);
        pxB[2] = pack2(b1v.x, b1v.x); pxB[3] = pack2(b1v.y, b1v.y);
        pxB[4] = pack2(b2v.x, b2v.x); pxB[5] = pack2(b2v.y, b2v.y);
    }

    __syncthreads();

    // ---- L3 accumulators (built incrementally across the two L2 halves) ----
    ull h3A[8], h3B[8];
    {
        const ulonglong2* bias = reinterpret_cast<const ulonglong2*>(sb3);
        #pragma unroll
        for (int q = 0; q < 4; q++) {
            ulonglong2 t = bias[q];
            h3A[2 * q] = t.x; h3A[2 * q + 1] = t.y;
            h3B[2 * q] = t.x; h3B[2 * q + 1] = t.y;
        }
    }

    // ---- two halves of the L2 output (16 outputs each); L1 recomputed per half ----
    #pragma unroll
    for (int half = 0; half < 2; half++) {
        ull accA[8], accB[8];
        {
            const ulonglong2* bias = reinterpret_cast<const ulonglong2*>(sb2 + 16 * half);
            #pragma unroll
            for (int q = 0; q < 4; q++) {
                ulonglong2 t = bias[q];
                accA[2 * q] = t.x; accA[2 * q + 1] = t.y;
                accB[2 * q] = t.x; accB[2 * q + 1] = t.y;
            }
        }
        // fused L1 (6->64 as 32 output-pairs) + half of L2 (64->16)
        #pragma unroll 16
        for (int jp = 0; jp < 32; jp++) {
            ull bp = sb1p[jp];
            const ulonglong2* w1 = reinterpret_cast<const ulonglong2*>(sW1t + jp * 12);
            ulonglong2 wa = w1[0], wb = w1[1], wc = w1[2];
            ull hA = fma2(pxA[0], wa.x, bp);
            hA = fma2(pxA[1], wa.y, hA);
            hA = fma2(pxA[2], wb.x, hA);
            hA = fma2(pxA[3], wb.y, hA);
            hA = fma2(pxA[4], wc.x, hA);
            hA = fma2(pxA[5], wc.y, hA);
            ull hB = fma2(pxB[0], wa.x, bp);
            hB = fma2(pxB[1], wa.y, hB);
            hB = fma2(pxB[2], wb.x, hB);
            hB = fma2(pxB[3], wb.y, hB);
            hB = fma2(pxB[4], wc.x, hB);
            hB = fma2(pxB[5], wc.y, hB);
            float h0A, h1A, h0B, h1B;
            unpack2(hA, h0A, h1A);
            unpack2(hB, h0B, h1B);
            h0A = fmaxf(h0A, 0.0f); h1A = fmaxf(h1A, 0.0f);
            h0B = fmaxf(h0B, 0.0f); h1B = fmaxf(h1B, 0.0f);
            // j = 2*jp
            {
                ull paa = pack2(h0A, h0A), pbb = pack2(h0B, h0B);
                const ulonglong2* w2 = reinterpret_cast<const ulonglong2*>(sW2 + (2 * jp) * 32 + 16 * half);
                #pragma unroll
                for (int q = 0; q < 4; q++) {
                    ulonglong2 w = w2[q];
                    accA[2 * q]     = fma2(paa, w.x, accA[2 * q]);
                    accA[2 * q + 1] = fma2(paa, w.y, accA[2 * q + 1]);
                    accB[2 * q]     = fma2(pbb, w.x, accB[2 * q]);
                    accB[2 * q + 1] = fma2(pbb, w.y, accB[2 * q + 1]);
                }
            }
            // j = 2*jp + 1
            {
                ull paa = pack2(h1A, h1A), pbb = pack2(h1B, h1B);
                const ulonglong2* w2 = reinterpret_cast<const ulonglong2*>(sW2 + (2 * jp + 1) * 32 + 16 * half);
                #pragma unroll
                for (int q = 0; q < 4; q++) {
                    ulonglong2 w = w2[q];
                    accA[2 * q]     = fma2(paa, w.x, accA[2 * q]);
                    accA[2 * q + 1] = fma2(paa, w.y, accA[2 * q + 1]);
                    accB[2 * q]     = fma2(pbb, w.x, accB[2 * q]);
                    accB[2 * q + 1] = fma2(pbb, w.y, accB[2 * q + 1]);
                }
            }
        }
        // L3 partial: consume this half's 16 outputs immediately (explicit s=0/s=1)
        #pragma unroll
        for (int p = 0; p < 8; p++) {
            float a0f, a1f, b0f, b1f;
            unpack2(accA[p], a0f, a1f);
            unpack2(accB[p], b0f, b1f);
            a0f = fmaxf(a0f, 0.0f); a1f = fmaxf(a1f, 0.0f);
            b0f = fmaxf(b0f, 0.0f); b1f = fmaxf(b1f, 0.0f);
            {
                const int j3 = 16 * half + 2 * p;
                ull paa = pack2(a0f, a0f), pbb = pack2(b0f, b0f);
                const ulonglong2* w3 = reinterpret_cast<const ulonglong2*>(sW3 + j3 * 16);
                #pragma unroll
                for (int q = 0; q < 4; q++) {
                    ulonglong2 w = w3[q];
                    h3A[2 * q]     = fma2(paa, w.x, h3A[2 * q]);
                    h3A[2 * q + 1] = fma2(paa, w.y, h3A[2 * q + 1]);
                    h3B[2 * q]     = fma2(pbb, w.x, h3B[2 * q]);
                    h3B[2 * q + 1] = fma2(pbb, w.y, h3B[2 * q + 1]);
                }
            }
            {
                const int j3 = 16 * half + 2 * p + 1;
                ull paa = pack2(a1f, a1f), pbb = pack2(b1f, b1f);
                const ulonglong2* w3 = reinterpret_cast<const ulonglong2*>(sW3 + j3 * 16);
                #pragma unroll
                for (int q = 0; q < 4; q++) {
                    ulonglong2 w = w3[q];
                    h3A[2 * q]     = fma2(paa, w.x, h3A[2 * q]);
                    h3A[2 * q + 1] = fma2(paa, w.y, h3A[2 * q + 1]);
                    h3B[2 * q]     = fma2(pbb, w.x, h3B[2 * q]);
                    h3B[2 * q + 1] = fma2(pbb, w.y, h3B[2 * q + 1]);
                }
            }
        }
    }

    // ---- L4 (16->9, padded 12), explicit s=0/s=1 ----
    ull pAa[6], pBa[6];
    {
        const ulonglong2* bias = reinterpret_cast<const ulonglong2*>(sb4);
        #pragma unroll
        for (int q = 0; q < 3; q++) {
            ulonglong2 t = bias[q];
            pAa[2 * q] = t.x; pAa[2 * q + 1] = t.y;
            pBa[2 * q] = t.x; pBa[2 * q + 1] = t.y;
        }
    }
    #pragma unroll
    for (int jp = 0; jp < 8; jp++) {
        float a0f, a1f, b0f, b1f;
        unpack2(h3A[jp], a0f, a1f);
        unpack2(h3B[jp], b0f, b1f);
        a0f = fmaxf(a0f, 0.0f); a1f = fmaxf(a1f, 0.0f);
        b0f = fmaxf(b0f, 0.0f); b1f = fmaxf(b1f, 0.0f);
        {
            const int j = 2 * jp;
            ull paa = pack2(a0f, a0f), pbb = pack2(b0f, b0f);
            const ulonglong2* w4 = reinterpret_cast<const ulonglong2*>(sW4 + j * 12);
            #pragma unroll
            for (int q = 0; q < 3; q++) {
                ulonglong2 w = w4[q];
                pAa[2 * q]     = fma2(paa, w.x, pAa[2 * q]);
                pAa[2 * q + 1] = fma2(paa, w.y, pAa[2 * q + 1]);
                pBa[2 * q]     = fma2(pbb, w.x, pBa[2 * q]);
                pBa[2 * q + 1] = fma2(pbb, w.y, pBa[2 * q + 1]);
            }
        }
        {
            const int j = 2 * jp + 1;
            ull paa = pack2(a1f, a1f), pbb = pack2(b1f, b1f);
            const ulonglong2* w4 = reinterpret_cast<const ulonglong2*>(sW4 + j * 12);
            #pragma unroll
            for (int q = 0; q < 3; q++) {
                ulonglong2 w = w4[q];
                pAa[2 * q]     = fma2(paa, w.x, pAa[2 * q]);
                pAa[2 * q + 1] = fma2(paa, w.y, pAa[2 * q + 1]);
                pBa[2 * q]     = fma2(pbb, w.x, pBa[2 * q]);
                pBa[2 * q + 1] = fma2(pbb, w.y, pBa[2 * q + 1]);
            }
        }
    }

    float parsA[12], parsB[12];
    #pragma unroll
    for (int q = 0; q < 6; q++) {
        unpack2(pAa[q], parsA[2 * q], parsA[2 * q + 1]);
        unpack2(pBa[q], parsB[2 * q], parsB[2 * q + 1]);
    }

    // ---- head math (margins reloaded from gmem; packed over the row pair) ----
    ull A00 = pack2(__expf(parsA[0]), __expf(parsB[0]));
    ull A01 = pack2(__expf(parsA[1]), __expf(parsB[1]));
    ull A10 = pack2(__expf(parsA[2]), __expf(parsB[2]));
    ull A11 = pack2(__expf(parsA[3]), __expf(parsB[3]));
    const ull ONE = pack2(1.0f, 1.0f);
    ull A02 = ONE, A12 = ONE, A20 = ONE, A21 = ONE, A22 = ONE;

    float shm0A = 0.02f + 0.96f * frcp(1.0f + __expf(-parsA[4]));
    float shm1A = 0.02f + 0.96f * frcp(1.0f + __expf(-parsA[5]));
    float shf0A = 0.02f + 0.96f * frcp(1.0f + __expf(-parsA[6]));
    float shf1A = 0.02f + 0.96f * frcp(1.0f + __expf(-parsA[7]));
    float shm0B = 0.02f + 0.96f * frcp(1.0f + __expf(-parsB[4]));
    float shm1B = 0.02f + 0.96f * frcp(1.0f + __expf(-parsB[5]));
    float shf0B = 0.02f + 0.96f * frcp(1.0f + __expf(-parsB[6]));
    float shf1B = 0.02f + 0.96f * frcp(1.0f + __expf(-parsB[7]));
    float VA = __expf(parsA[8]), VB = __expf(parsB[8]);

    float2 a0 = m2[rowA * 3 + 0], a1 = m2[rowA * 3 + 1], a2 = m2[rowA * 3 + 2];
    float2 b0 = m2[rowB * 3 + 0], b1v = m2[rowB * 3 + 1], b2v = m2[rowB * 3 + 2];
    float xA[6] = { a0.x, a0.y, a1.x, a1.y, a2.x, a2.y };
    float xB[6] = { b0.x, b0.y, b1v.x, b1v.y, b2v.x, b2v.y };

    ull M0 = pack2(xA[0], xB[0]), M1 = pack2(xA[1], xB[1]), M2 = pack2(xA[2], xB[2]);
    ull F0 = pack2(xA[3], xB[3]), F1 = pack2(xA[4], xB[4]), F2 = pack2(xA[5], xB[5]);
    ull r0 = mul2(M0, pack2(shm0A, shm0B));
    ull r1 = mul2(M1, pack2(shm1A, shm1B));
    ull r2 = M2;
    ull c0 = mul2(F0, pack2(shf0A, shf0B));
    ull c1 = mul2(F1, pack2(shf1A, shf1B));
    ull c2 = F2;

    float um0A = xA[0] * (1.0f - shm0A), um1A = xA[1] * (1.0f - shm1A);
    float uf0A = xA[3] * (1.0f - shf0A), uf1A = xA[4] * (1.0f - shf1A);
    float um0B = xB[0] * (1.0f - shm0B), um1B = xB[1] * (1.0f - shm1B);
    float uf0B = xB[3] * (1.0f - shf0B), uf1B = xB[4] * (1.0f - shf1B);

    // EPS dropped: sums are bounded below by ~1e-2 (margins >= 0.05, sh >= 0.02),
    // so the 1e-12 epsilon perturbs results by < 1e-10 relative — far below 1e-3.
    #pragma unroll
    for (int it = 0; it < 10; it++) {
        ull s0 = add2(add2(A00, A01), A02);
        ull s1 = add2(add2(A10, A11), A12);
        ull s2 = add2(add2(A20, A21), A22);
        float l, h;
        unpack2(s0, l, h); ull i0 = pack2(frcp(l), frcp(h));
        unpack2(s1, l, h); ull i1 = pack2(frcp(l), frcp(h));
        unpack2(s2, l, h); ull i2 = pack2(frcp(l), frcp(h));
        ull f0 = mul2(r0, i0), f1 = mul2(r1, i1), f2 = mul2(r2, i2);
        A00 = mul2(A00, f0); A01 = mul2(A01, f0); A02 = mul2(A02, f0);
        A10 = mul2(A10, f1); A11 = mul2(A11, f1); A12 = mul2(A12, f1);
        A20 = mul2(A20, f2); A21 = mul2(A21, f2); A22 = mul2(A22, f2);
        ull t0 = add2(add2(A00, A10), A20);
        ull t1 = add2(add2(A01, A11), A21);
        ull t2 = add2(add2(A02, A12), A22);
        unpack2(t0, l, h); ull j0 = pack2(frcp(l), frcp(h));
        unpack2(t1, l, h); ull j1 = pack2(frcp(l), frcp(h));
        unpack2(t2, l, h); ull j2 = pack2(frcp(l), frcp(h));
        ull g0 = mul2(c0, j0), g1 = mul2(c1, j1), g2 = mul2(c2, j2);
        A00 = mul2(A00, g0); A10 = mul2(A10, g0); A20 = mul2(A20, g0);
        A01 = mul2(A01, g1); A11 = mul2(A11, g1); A21 = mul2(A21, g1);
        A02 = mul2(A02, g2); A12 = mul2(A12, g2); A22 = mul2(A22, g2);
    }

    float o00, o01, o02, o10, o11, o12, o20, o21, o22;
    float q00, q01, q02, q10, q11, q12, q20, q21, q22;
    unpack2(A00, o00, q00); unpack2(A01, o01, q01); unpack2(A02, o02, q02);
    unpack2(A10, o10, q10); unpack2(A11, o11, q11); unpack2(A12, o12, q12);
    unpack2(A20, o20, q20); unpack2(A21, o21, q21); unpack2(A22, o22, q22);

    float4* oA = reinterpret_cast<float4*>(out_mus + (size_t)rowA * 16);
    oA[0] = make_float4(o00, o01, o02, um0A);
    oA[1] = make_float4(o10, o11, o12, um1A);
    oA[2] = make_float4(o20, o21, o22, 0.0f);
    oA[3] = make_float4(uf0A, uf1A, 0.0f, 0.0f);
    out_V[rowA] = VA;

    float4* oB = reinterpret_cast<float4*>(out_mus + (size_t)rowB * 16);
    oB[0] = make_float4(q00, q01, q02, um0B);
    oB[1] = make_float4(q10, q11, q12, um1B);
    oB[2] = make_float4(q20, q21, q22, 0.0f);
    oB[3] = make_float4(uf0B, uf1B, 0.0f, 0.0f);
    out_V[rowB] = VB;
}

extern "C" void kernel_launch(void* const* d_in, const int* in_sizes, int n_in,
                              void* d_out, int out_size)
{
    const float* margins = (const float*)d_in[0];
    const float* W1 = (const float*)d_in[1];
    const float* b1 = (const float*)d_in[2];
    const float* W2 = (const float*)d_in[3];
    const float* b2 = (const float*)d_in[4];
    const float* W3 = (const float*)d_in[5];
    const float* b3 = (const float*)d_in[6];
    const float* W4 = (const float*)d_in[7];
    const float* b4 = (const float*)d_in[8];

    int B = in_sizes[0] / 6;
    float* out_mus = (float*)d_out;
    float* out_V = (float*)d_out + (size_t)B * 16;

    int rows_per_block = 2 * THREADS;
    int blocks = (B + rows_per_block - 1) / rows_per_block;
    sinkhorn_unmatched_kernel<<<blocks, THREADS>>>(
        margins, W1, b1, W2, b2, W3, b3, W4, b4, out_mus, out_V, B);
}

// round 17
// speedup vs baseline: 1.4619x; 1.1308x over previous
#include <cuda_runtime.h>

#define THREADS 128

typedef unsigned long long ull;

// ---- f32x2 packed helpers (sm_103a) ----
__device__ __forceinline__ ull pack2(float lo, float hi) {
    ull r; asm("mov.b64 %0, {%1, %2};" : "=l"(r) : "f"(lo), "f"(hi)); return r;
}
__device__ __forceinline__ void unpack2(ull p, float& lo, float& hi) {
    asm("mov.b64 {%0, %1}, %2;" : "=f"(lo), "=f"(hi) : "l"(p));
}
__device__ __forceinline__ ull fma2(ull a, ull b, ull c) {
    ull d; asm("fma.rn.f32x2 %0, %1, %2, %3;" : "=l"(d) : "l"(a), "l"(b), "l"(c)); return d;
}
__device__ __forceinline__ ull add2(ull a, ull b) {
    ull d; asm("add.rn.f32x2 %0, %1, %2;" : "=l"(d) : "l"(a), "l"(b)); return d;
}
__device__ __forceinline__ ull mul2(ull a, ull b) {
    ull d; asm("mul.rn.f32x2 %0, %1, %2;" : "=l"(d) : "l"(a), "l"(b)); return d;
}
__device__ __forceinline__ float frcp(float x) {
    float y; asm("rcp.approx.f32 %0, %1;" : "=f"(y) : "f"(x)); return y;
}

__global__ __launch_bounds__(THREADS, 5)
void sinkhorn_unmatched_kernel(
    const float* __restrict__ margins,
    const float* __restrict__ W1, const float* __restrict__ b1,
    const float* __restrict__ W2, const float* __restrict__ b2,
    const float* __restrict__ W3, const float* __restrict__ b3,
    const float* __restrict__ W4, const float* __restrict__ b4,
    float* __restrict__ out_mus, float* __restrict__ out_V, int B)
{
    // W1 transposed into output-pair rows: sW1t[jp][2*i+s] = W1[i][2*jp+s]
    __shared__ float sW1t[32 * 12];
    __shared__ ull   sb1p[32];        // (b1[2jp], b1[2jp+1])
    __shared__ float sW2[64 * 32];
    __shared__ float sb2[32];
    __shared__ float sW3[32 * 16];
    __shared__ float sb3[16];
    __shared__ float sW4[16 * 12];
    __shared__ float sb4[12];

    const int tid = threadIdx.x;
    for (int i = tid; i < 32 * 12; i += THREADS) {
        int jp = i / 12, t = i % 12;
        int in = t >> 1, s = t & 1;
        sW1t[i] = W1[in * 64 + 2 * jp + s];
    }
    for (int i = tid; i < 32; i += THREADS) sb1p[i] = pack2(b1[2 * i], b1[2 * i + 1]);
    for (int i = tid; i < 64 * 32; i += THREADS) sW2[i] = W2[i];
    for (int i = tid; i < 32; i += THREADS) sb2[i] = b2[i];
    for (int i = tid; i < 32 * 16; i += THREADS) sW3[i] = W3[i];
    for (int i = tid; i < 16; i += THREADS) sb3[i] = b3[i];
    for (int i = tid; i < 16 * 12; i += THREADS) {
        int r = i / 12, c = i % 12;
        sW4[i] = (c < 9) ? W4[r * 9 + c] : 0.0f;
    }
    for (int i = tid; i < 12; i += THREADS) sb4[i] = (i < 9) ? b4[i] : 0.0f;

    int rowA = blockIdx.x * (2 * THREADS) + tid;
    int rowB = rowA + THREADS;
    if (rowA >= B) { __syncthreads(); return; }
    if (rowB >= B) rowB = rowA;

    // margins: self-duplicated pairs per row (live through the L1/L2 loops)
    const float2* m2 = reinterpret_cast<const float2*>(margins);
    ull pxA[6], pxB[6];
    {
        float2 a0 = m2[rowA * 3 + 0], a1 = m2[rowA * 3 + 1], a2 = m2[rowA * 3 + 2];
        float2 b0 = m2[rowB * 3 + 0], b1v = m2[rowB * 3 + 1], b2v = m2[rowB * 3 + 2];
        pxA[0] = pack2(a0.x, a0.x);   pxA[1] = pack2(a0.y, a0.y);
        pxA[2] = pack2(a1.x, a1.x);   pxA[3] = pack2(a1.y, a1.y);
        pxA[4] = pack2(a2.x, a2.x);   pxA[5] = pack2(a2.y, a2.y);
        pxB[0] = pack2(b0.x, b0.x);   pxB[1] = pack2(b0.y, b0.y);
        pxB[2] = pack2(b1v.x, b1v.x); pxB[3] = pack2(b1v.y, b1v.y);
        pxB[4] = pack2(b2v.x, b2v.x); pxB[5] = pack2(b2v.y, b2v.y);
    }

    __syncthreads();

    // ---- L3 accumulators (built incrementally across the two L2 halves) ----
    ull h3A[8], h3B[8];
    {
        const ulonglong2* bias = reinterpret_cast<const ulonglong2*>(sb3);
        #pragma unroll
        for (int q = 0; q < 4; q++) {
            ulonglong2 t = bias[q];
            h3A[2 * q] = t.x; h3A[2 * q + 1] = t.y;
            h3B[2 * q] = t.x; h3B[2 * q + 1] = t.y;
        }
    }

    // ---- two halves of the L2 output (16 outputs each); L1 recomputed per half ----
    #pragma unroll
    for (int half = 0; half < 2; half++) {
        ull accA[8], accB[8];
        {
            const ulonglong2* bias = reinterpret_cast<const ulonglong2*>(sb2 + 16 * half);
            #pragma unroll
            for (int q = 0; q < 4; q++) {
                ulonglong2 t = bias[q];
                accA[2 * q] = t.x; accA[2 * q + 1] = t.y;
                accB[2 * q] = t.x; accB[2 * q + 1] = t.y;
            }
        }
        // fused L1 (6->64 as 32 output-pairs) + half of L2 (64->16)
        #pragma unroll 8
        for (int jp = 0; jp < 32; jp++) {
            const ulonglong2* w1 = reinterpret_cast<const ulonglong2*>(sW1t + jp * 12);
            ulonglong2 wa = w1[0], wb = w1[1], wc = w1[2];
            ull bp = sb1p[jp];
            ull hA = fma2(pxA[0], wa.x, bp);
            hA = fma2(pxA[1], wa.y, hA);
            hA = fma2(pxA[2], wb.x, hA);
            hA = fma2(pxA[3], wb.y, hA);
            hA = fma2(pxA[4], wc.x, hA);
            hA = fma2(pxA[5], wc.y, hA);
            ull hB = fma2(pxB[0], wa.x, bp);
            hB = fma2(pxB[1], wa.y, hB);
            hB = fma2(pxB[2], wb.x, hB);
            hB = fma2(pxB[3], wb.y, hB);
            hB = fma2(pxB[4], wc.x, hB);
            hB = fma2(pxB[5], wc.y, hB);
            float h0A, h1A, h0B, h1B;
            unpack2(hA, h0A, h1A);
            unpack2(hB, h0B, h1B);
            h0A = fmaxf(h0A, 0.0f); h1A = fmaxf(h1A, 0.0f);
            h0B = fmaxf(h0B, 0.0f); h1B = fmaxf(h1B, 0.0f);
            // j = 2*jp
            {
                ull paa = pack2(h0A, h0A), pbb = pack2(h0B, h0B);
                const ulonglong2* w2 = reinterpret_cast<const ulonglong2*>(sW2 + (2 * jp) * 32 + 16 * half);
                #pragma unroll
                for (int q = 0; q < 4; q++) {
                    ulonglong2 w = w2[q];
                    accA[2 * q]     = fma2(paa, w.x, accA[2 * q]);
                    accA[2 * q + 1] = fma2(paa, w.y, accA[2 * q + 1]);
                    accB[2 * q]     = fma2(pbb, w.x, accB[2 * q]);
                    accB[2 * q + 1] = fma2(pbb, w.y, accB[2 * q + 1]);
                }
            }
            // j = 2*jp + 1
            {
                ull paa = pack2(h1A, h1A), pbb = pack2(h1B, h1B);
                const ulonglong2* w2 = reinterpret_cast<const ulonglong2*>(sW2 + (2 * jp + 1) * 32 + 16 * half);
                #pragma unroll
                for (int q = 0; q < 4; q++) {
                    ulonglong2 w = w2[q];
                    accA[2 * q]     = fma2(paa, w.x, accA[2 * q]);
                    accA[2 * q + 1] = fma2(paa, w.y, accA[2 * q + 1]);
                    accB[2 * q]     = fma2(pbb, w.x, accB[2 * q]);
                    accB[2 * q + 1] = fma2(pbb, w.y, accB[2 * q + 1]);
                }
            }
        }
        // L3 partial: consume this half's 16 outputs immediately (explicit s=0/s=1)
        #pragma unroll
        for (int p = 0; p < 8; p++) {
            float a0f, a1f, b0f, b1f;
            unpack2(accA[p], a0f, a1f);
            unpack2(accB[p], b0f, b1f);
            a0f = fmaxf(a0f, 0.0f); a1f = fmaxf(a1f, 0.0f);
            b0f = fmaxf(b0f, 0.0f); b1f = fmaxf(b1f, 0.0f);
            {
                const int j3 = 16 * half + 2 * p;
                ull paa = pack2(a0f, a0f), pbb = pack2(b0f, b0f);
                const ulonglong2* w3 = reinterpret_cast<const ulonglong2*>(sW3 + j3 * 16);
                #pragma unroll
                for (int q = 0; q < 4; q++) {
                    ulonglong2 w = w3[q];
                    h3A[2 * q]     = fma2(paa, w.x, h3A[2 * q]);
                    h3A[2 * q + 1] = fma2(paa, w.y, h3A[2 * q + 1]);
                    h3B[2 * q]     = fma2(pbb, w.x, h3B[2 * q]);
                    h3B[2 * q + 1] = fma2(pbb, w.y, h3B[2 * q + 1]);
                }
            }
            {
                const int j3 = 16 * half + 2 * p + 1;
                ull paa = pack2(a1f, a1f), pbb = pack2(b1f, b1f);
                const ulonglong2* w3 = reinterpret_cast<const ulonglong2*>(sW3 + j3 * 16);
                #pragma unroll
                for (int q = 0; q < 4; q++) {
                    ulonglong2 w = w3[q];
                    h3A[2 * q]     = fma2(paa, w.x, h3A[2 * q]);
                    h3A[2 * q + 1] = fma2(paa, w.y, h3A[2 * q + 1]);
                    h3B[2 * q]     = fma2(pbb, w.x, h3B[2 * q]);
                    h3B[2 * q + 1] = fma2(pbb, w.y, h3B[2 * q + 1]);
                }
            }
        }
    }

    // ---- L4 (16->9, padded 12), explicit s=0/s=1 ----
    ull pAa[6], pBa[6];
    {
        const ulonglong2* bias = reinterpret_cast<const ulonglong2*>(sb4);
        #pragma unroll
        for (int q = 0; q < 3; q++) {
            ulonglong2 t = bias[q];
            pAa[2 * q] = t.x; pAa[2 * q + 1] = t.y;
            pBa[2 * q] = t.x; pBa[2 * q + 1] = t.y;
        }
    }
    #pragma unroll
    for (int jp = 0; jp < 8; jp++) {
        float a0f, a1f, b0f, b1f;
        unpack2(h3A[jp], a0f, a1f);
        unpack2(h3B[jp], b0f, b1f);
        a0f = fmaxf(a0f, 0.0f); a1f = fmaxf(a1f, 0.0f);
        b0f = fmaxf(b0f, 0.0f); b1f = fmaxf(b1f, 0.0f);
        {
            const int j = 2 * jp;
            ull paa = pack2(a0f, a0f), pbb = pack2(b0f, b0f);
            const ulonglong2* w4 = reinterpret_cast<const ulonglong2*>(sW4 + j * 12);
            #pragma unroll
            for (int q = 0; q < 3; q++) {
                ulonglong2 w = w4[q];
                pAa[2 * q]     = fma2(paa, w.x, pAa[2 * q]);
                pAa[2 * q + 1] = fma2(paa, w.y, pAa[2 * q + 1]);
                pBa[2 * q]     = fma2(pbb, w.x, pBa[2 * q]);
                pBa[2 * q + 1] = fma2(pbb, w.y, pBa[2 * q + 1]);
            }
        }
        {
            const int j = 2 * jp + 1;
            ull paa = pack2(a1f, a1f), pbb = pack2(b1f, b1f);
            const ulonglong2* w4 = reinterpret_cast<const ulonglong2*>(sW4 + j * 12);
            #pragma unroll
            for (int q = 0; q < 3; q++) {
                ulonglong2 w = w4[q];
                pAa[2 * q]     = fma2(paa, w.x, pAa[2 * q]);
                pAa[2 * q + 1] = fma2(paa, w.y, pAa[2 * q + 1]);
                pBa[2 * q]     = fma2(pbb, w.x, pBa[2 * q]);
                pBa[2 * q + 1] = fma2(pbb, w.y, pBa[2 * q + 1]);
            }
        }
    }

    float parsA[12], parsB[12];
    #pragma unroll
    for (int q = 0; q < 6; q++) {
        unpack2(pAa[q], parsA[2 * q], parsA[2 * q + 1]);
        unpack2(pBa[q], parsB[2 * q], parsB[2 * q + 1]);
    }

    // ---- head math (margins reloaded from gmem; packed over the row pair) ----
    ull A00 = pack2(__expf(parsA[0]), __expf(parsB[0]));
    ull A01 = pack2(__expf(parsA[1]), __expf(parsB[1]));
    ull A10 = pack2(__expf(parsA[2]), __expf(parsB[2]));
    ull A11 = pack2(__expf(parsA[3]), __expf(parsB[3]));
    const ull ONE = pack2(1.0f, 1.0f);
    ull A02 = ONE, A12 = ONE, A20 = ONE, A21 = ONE, A22 = ONE;

    float shm0A = 0.02f + 0.96f * frcp(1.0f + __expf(-parsA[4]));
    float shm1A = 0.02f + 0.96f * frcp(1.0f + __expf(-parsA[5]));
    float shf0A = 0.02f + 0.96f * frcp(1.0f + __expf(-parsA[6]));
    float shf1A = 0.02f + 0.96f * frcp(1.0f + __expf(-parsA[7]));
    float shm0B = 0.02f + 0.96f * frcp(1.0f + __expf(-parsB[4]));
    float shm1B = 0.02f + 0.96f * frcp(1.0f + __expf(-parsB[5]));
    float shf0B = 0.02f + 0.96f * frcp(1.0f + __expf(-parsB[6]));
    float shf1B = 0.02f + 0.96f * frcp(1.0f + __expf(-parsB[7]));
    float VA = __expf(parsA[8]), VB = __expf(parsB[8]);

    float2 a0 = m2[rowA * 3 + 0], a1 = m2[rowA * 3 + 1], a2 = m2[rowA * 3 + 2];
    float2 b0 = m2[rowB * 3 + 0], b1v = m2[rowB * 3 + 1], b2v = m2[rowB * 3 + 2];
    float xA[6] = { a0.x, a0.y, a1.x, a1.y, a2.x, a2.y };
    float xB[6] = { b0.x, b0.y, b1v.x, b1v.y, b2v.x, b2v.y };

    ull M0 = pack2(xA[0], xB[0]), M1 = pack2(xA[1], xB[1]), M2 = pack2(xA[2], xB[2]);
    ull F0 = pack2(xA[3], xB[3]), F1 = pack2(xA[4], xB[4]), F2 = pack2(xA[5], xB[5]);
    ull r0 = mul2(M0, pack2(shm0A, shm0B));
    ull r1 = mul2(M1, pack2(shm1A, shm1B));
    ull r2 = M2;
    ull c0 = mul2(F0, pack2(shf0A, shf0B));
    ull c1 = mul2(F1, pack2(shf1A, shf1B));
    ull c2 = F2;

    float um0A = xA[0] * (1.0f - shm0A), um1A = xA[1] * (1.0f - shm1A);
    float uf0A = xA[3] * (1.0f - shf0A), uf1A = xA[4] * (1.0f - shf1A);
    float um0B = xB[0] * (1.0f - shm0B), um1B = xB[1] * (1.0f - shm1B);
    float uf0B = xB[3] * (1.0f - shf0B), uf1B = xB[4] * (1.0f - shf1B);

    // EPS dropped: sums bounded below by ~1e-2 (margins >= 0.05, sh >= 0.02),
    // so the 1e-12 epsilon perturbs results by < 1e-10 relative (validated R16:
    // rel_err identical with and without).
    #pragma unroll
    for (int it = 0; it < 10; it++) {
        ull s0 = add2(add2(A00, A01), A02);
        ull s1 = add2(add2(A10, A11), A12);
        ull s2 = add2(add2(A20, A21), A22);
        float l, h;
        unpack2(s0, l, h); ull i0 = pack2(frcp(l), frcp(h));
        unpack2(s1, l, h); ull i1 = pack2(frcp(l), frcp(h));
        unpack2(s2, l, h); ull i2 = pack2(frcp(l), frcp(h));
        ull f0 = mul2(r0, i0), f1 = mul2(r1, i1), f2 = mul2(r2, i2);
        A00 = mul2(A00, f0); A01 = mul2(A01, f0); A02 = mul2(A02, f0);
        A10 = mul2(A10, f1); A11 = mul2(A11, f1); A12 = mul2(A12, f1);
        A20 = mul2(A20, f2); A21 = mul2(A21, f2); A22 = mul2(A22, f2);
        ull t0 = add2(add2(A00, A10), A20);
        ull t1 = add2(add2(A01, A11), A21);
        ull t2 = add2(add2(A02, A12), A22);
        unpack2(t0, l, h); ull j0 = pack2(frcp(l), frcp(h));
        unpack2(t1, l, h); ull j1 = pack2(frcp(l), frcp(h));
        unpack2(t2, l, h); ull j2 = pack2(frcp(l), frcp(h));
        ull g0 = mul2(c0, j0), g1 = mul2(c1, j1), g2 = mul2(c2, j2);
        A00 = mul2(A00, g0); A10 = mul2(A10, g0); A20 = mul2(A20, g0);
        A01 = mul2(A01, g1); A11 = mul2(A11, g1); A21 = mul2(A21, g1);
        A02 = mul2(A02, g2); A12 = mul2(A12, g2); A22 = mul2(A22, g2);
    }

    float o00, o01, o02, o10, o11, o12, o20, o21, o22;
    float q00, q01, q02, q10, q11, q12, q20, q21, q22;
    unpack2(A00, o00, q00); unpack2(A01, o01, q01); unpack2(A02, o02, q02);
    unpack2(A10, o10, q10); unpack2(A11, o11, q11); unpack2(A12, o12, q12);
    unpack2(A20, o20, q20); unpack2(A21, o21, q21); unpack2(A22, o22, q22);

    float4* oA = reinterpret_cast<float4*>(out_mus + (size_t)rowA * 16);
    oA[0] = make_float4(o00, o01, o02, um0A);
    oA[1] = make_float4(o10, o11, o12, um1A);
    oA[2] = make_float4(o20, o21, o22, 0.0f);
    oA[3] = make_float4(uf0A, uf1A, 0.0f, 0.0f);
    out_V[rowA] = VA;

    float4* oB = reinterpret_cast<float4*>(out_mus + (size_t)rowB * 16);
    oB[0] = make_float4(q00, q01, q02, um0B);
    oB[1] = make_float4(q10, q11, q12, um1B);
    oB[2] = make_float4(q20, q21, q22, 0.0f);
    oB[3] = make_float4(uf0B, uf1B, 0.0f, 0.0f);
    out_V[rowB] = VB;
}

extern "C" void kernel_launch(void* const* d_in, const int* in_sizes, int n_in,
                              void* d_out, int out_size)
{
    const float* margins = (const float*)d_in[0];
    const float* W1 = (const float*)d_in[1];
    const float* b1 = (const float*)d_in[2];
    const float* W2 = (const float*)d_in[3];
    const float* b2 = (const float*)d_in[4];
    const float* W3 = (const float*)d_in[5];
    const float* b3 = (const float*)d_in[6];
    const float* W4 = (const float*)d_in[7];
    const float* b4 = (const float*)d_in[8];

    int B = in_sizes[0] / 6;
    float* out_mus = (float*)d_out;
    float* out_V = (float*)d_out + (size_t)B * 16;

    int rows_per_block = 2 * THREADS;
    int blocks = (B + rows_per_block - 1) / rows_per_block;
    sinkhorn_unmatched_kernel<<<blocks, THREADS>>>(
        margins, W1, b1, W2, b2, W3, b3, W4, b4, out_mus, out_V, B);
}